// round 16
// baseline (speedup 1.0000x reference)
#include <cuda_runtime.h>
#include <math.h>

#define TLEN 2048
#define BATCH 64
#define HID 50
#define G3 150
#define XGS 152
#define DIN0 128

typedef unsigned long long u64;

// scratch (device globals: allocation-free rule)
__device__ float g_buf0[TLEN*BATCH*HID];
__device__ float g_buf1[TLEN*BATCH*HID];
__device__ float g_xg[TLEN*BATCH*XGS];
__device__ float g_h1[4*BATCH*1600];     // 4 split-K partials

// sigmoid via HW tanh: 1 MUFU instead of EX2+RCP. |err| <= ~2.5e-4.
__device__ __forceinline__ float sigt(float x){
    float t;
    asm("tanh.approx.f32 %0, %1;" : "=f"(t) : "f"(0.5f*x));
    return fmaf(0.5f, t, 0.5f);
}
// accurate tanh for the candidate gate (2 MUFU, err ~1e-7)
__device__ __forceinline__ float tanhf_fast(float x){
    float e = __expf(2.0f*x);              // inf-safe
    return 1.0f - __fdividef(2.0f, e + 1.0f);
}
__device__ __forceinline__ void fma2(u64& d, u64 a, u64 b){
    asm("fma.rn.f32x2 %0, %1, %2, %0;" : "+l"(d) : "l"(a), "l"(b));
}
__device__ __forceinline__ void add2(u64& d, u64 a){
    asm("add.rn.f32x2 %0, %0, %1;" : "+l"(d) : "l"(a));
}
__device__ __forceinline__ u64 dup2(float x){
    u64 r; asm("mov.b64 %0, {%1, %1};" : "=l"(r) : "f"(x)); return r;
}
__device__ __forceinline__ u64 pack2(float a, float b){
    u64 r; asm("mov.b64 %0, {%1, %2};" : "=l"(r) : "f"(a), "f"(b)); return r;
}
__device__ __forceinline__ float2 unp2(u64 v){
    float2 r; asm("mov.b64 {%0, %1}, %2;" : "=f"(r.x), "=f"(r.y) : "l"(v)); return r;
}

// ---------------------------------------------------------------------------
// Layer-0 input-gate GEMM (K=128), coalesced stores via smem staging.
// ---------------------------------------------------------------------------
__global__ void __launch_bounds__(256,2)
xg_gemm_kernel(const float* __restrict__ x, const float* __restrict__ W,
               const float* __restrict__ bi, float* __restrict__ xg)
{
    extern __shared__ float sm[];
    float* Xs = sm;                  // 64 x 132
    float* Wk = sm + 8448;           // 32 x 160
    float* Ys = sm + 8448 + 5120;    // 64 x 152
    int t = blockIdx.x;
    int tid = threadIdx.x;
    int tm = tid >> 3;
    int tn = tid & 7;

    for (int p = tid; p < 64*DIN0; p += 256){
        int b = p >> 7, d = p & 127;
        Xs[b*132 + d] = x[(size_t)b*TLEN*DIN0 + (size_t)t*DIN0 + d];
    }
    u64 acc[2][10];
    #pragma unroll
    for (int i=0;i<2;i++)
        #pragma unroll
        for (int j=0;j<10;j++) acc[i][j]=0ull;

    for (int kc = 0; kc < DIN0; kc += 32){
        __syncthreads();
        for (int p = tid; p < 32*160; p += 256){
            int r = p/160, c = p - r*160;
            Wk[p] = (c < G3) ? W[(size_t)(kc+r)*G3 + c] : 0.f;
        }
        __syncthreads();
        #pragma unroll 4
        for (int kk = 0; kk < 32; kk++){
            u64 a0 = dup2(Xs[(2*tm)  *132 + kc+kk]);
            u64 a1 = dup2(Xs[(2*tm+1)*132 + kc+kk]);
            const ulonglong2* bp = (const ulonglong2*)(Wk + kk*160 + tn*20);
            #pragma unroll
            for (int q=0;q<5;q++){
                ulonglong2 w = bp[q];
                fma2(acc[0][2*q],   a0, w.x);
                fma2(acc[0][2*q+1], a0, w.y);
                fma2(acc[1][2*q],   a1, w.x);
                fma2(acc[1][2*q+1], a1, w.y);
            }
        }
    }
    __syncthreads();
    #pragma unroll
    for (int i=0;i<2;i++){
        int row = 2*tm+i;
        #pragma unroll
        for (int q=0;q<10;q++){
            float2 v = unp2(acc[i][q]);
            int c0 = tn*20 + 2*q;
            if (c0 < 152)
                Ys[row*152 + c0]   = (c0   < G3) ? v.x + bi[c0]   : 0.f;
            if (c0+1 < 152)
                Ys[row*152 + c0+1] = (c0+1 < G3) ? v.y + bi[c0+1] : 0.f;
        }
    }
    __syncthreads();
    float4* dst = (float4*)(xg + (size_t)t*64*XGS);
    const float4* srcy = (const float4*)Ys;
    for (int p = tid; p < (64*152)/4; p += 256) dst[p] = srcy[p];
}

// ---------------------------------------------------------------------------
// PRE scan (recurrent-only, gates precomputed). Champion config: S=2, W=4.
// ---------------------------------------------------------------------------
template<int S, int WARPS>
__global__ void __launch_bounds__(WARPS*32, 2)
scan_pre_kernel(const float* __restrict__ xg, const float* __restrict__ Ug,
                const float* __restrict__ bvec, float* __restrict__ out,
                int rate, int dn, int nGroups)
{
    extern __shared__ float sm[];
    float* Upk = sm;                          // 9600 floats
    float* poolf = sm + 9600;
    int tid = threadIdx.x, wid = tid>>5, lane = tid&31;
    u64* h2 = (u64*)poolf + (size_t)wid*(S*64);

    for (int idx = tid; idx < 9600; idx += WARPS*32){
        int g = idx/384, rem = idx - g*384;
        int ro = rem >> 7, rem2 = rem & 127;
        int li = rem2 >> 2, e = rem2 & 3;
        int k = 2*g + (e>>1), ch = li + 32*(e&1);
        Upk[idx] = (ch < 50) ? Ug[k*G3 + ro*50 + ch] : 0.f;
    }
    const bool v2 = lane < 18;
    const int c1 = lane, c2 = lane + 32;
    const int c2v = v2 ? c2 : c1;
    const float* br = bvec + G3;
    u64 bz  = pack2(br[c1],     br[c2v]);
    u64 brr = pack2(br[50+c1],  br[50+c2v]);
    u64 bhr = pack2(br[100+c1], br[100+c2v]);
    __syncthreads();

    for (int grp = blockIdx.x*WARPS + wid; grp < nGroups; grp += gridDim.x*WARPS){
        int q0 = grp*S;
        int b0 = q0 & 63, rr = q0 >> 6;
        u64 hcur[S];
        #pragma unroll
        for (int s=0;s<S;s++){
            hcur[s] = 0ull;
            h2[s*64 + c1] = 0ull;
            h2[s*64 + c2] = 0ull;
        }
        __syncwarp();
        u64 gz[S], gr[S], gh[S];
        #pragma unroll
        for (int s=0;s<S;s++){
            const float* s0 = xg + ((size_t)rr*64 + b0+s)*XGS;
            gz[s] = pack2(s0[c1],     s0[c2v]);
            gr[s] = pack2(s0[50+c1],  s0[50+c2v]);
            gh[s] = pack2(s0[100+c1], s0[100+c2v]);
        }
        for (int st=0; st<dn; st++){
            u64 az[S], ar[S], ahx[S], ahr[S];
            #pragma unroll
            for (int s=0;s<S;s++){
                az[s]=bz;  add2(az[s], gz[s]);
                ar[s]=brr; add2(ar[s], gr[s]);
                ahx[s]=gh[s];
                ahr[s]=bhr;
            }
            if (st+1 < dn){
                int t_in = (st+1)*rate + rr;
                #pragma unroll
                for (int s=0;s<S;s++){
                    const float* s0 = xg + ((size_t)t_in*64 + b0+s)*XGS;
                    gz[s] = pack2(s0[c1],     s0[c2v]);
                    gr[s] = pack2(s0[50+c1],  s0[50+c2v]);
                    gh[s] = pack2(s0[100+c1], s0[100+c2v]);
                }
            }
            #pragma unroll 5
            for (int g=0; g<25; g++){
                const float* ub = Upk + g*384 + lane*4;
                ulonglong2 uz = *(const ulonglong2*)(ub);
                ulonglong2 ur = *(const ulonglong2*)(ub + 128);
                ulonglong2 uh = *(const ulonglong2*)(ub + 256);
                #pragma unroll
                for (int s=0;s<S;s++){
                    ulonglong2 hh = *(const ulonglong2*)(h2 + s*64 + 2*g);
                    fma2(az[s],  hh.x, uz.x); fma2(az[s],  hh.y, uz.y);
                    fma2(ar[s],  hh.x, ur.x); fma2(ar[s],  hh.y, ur.y);
                    fma2(ahr[s], hh.x, uh.x); fma2(ahr[s], hh.y, uh.y);
                }
            }
            __syncwarp();
            int t_out = rr*dn + st;
            #pragma unroll
            for (int s=0;s<S;s++){
                float* op = out + ((size_t)t_out*64 + b0+s)*HID;
                float2 zz = unp2(az[s]); float z1 = sigt(zz.x), z2 = sigt(zz.y);
                float2 rv = unp2(ar[s]); float r1 = sigt(rv.x), r2 = sigt(rv.y);
                u64 tt = ahx[s]; fma2(tt, pack2(r1,r2), ahr[s]);
                float2 th = unp2(tt);
                float hh1 = tanhf_fast(th.x), hh2 = tanhf_fast(th.y);
                float2 ho = unp2(hcur[s]);
                float hn1 = hh1 + z1*(ho.x - hh1);
                float hn2 = hh2 + z2*(ho.y - hh2);
                hcur[s] = pack2(hn1, hn2);
                h2[s*64 + c1] = dup2(hn1);
                op[c1] = hn1;
                if (v2){
                    h2[s*64 + c2] = dup2(hn2);
                    op[c2] = hn2;
                }
            }
            __syncwarp();
        }
    }
}

// ---------------------------------------------------------------------------
// Persistent fused dilated-GRU scan (champion inner loops, hcur in regs).
// ---------------------------------------------------------------------------
template<int S, int WARPS, bool FUSED>
__global__ void __launch_bounds__(WARPS*32, 2)
scan_kernel(const float* __restrict__ xin, const float* __restrict__ Wg,
            const float* __restrict__ Ug, const float* __restrict__ bvec,
            float* __restrict__ out, int rate, int dn, int nGroups)
{
    extern __shared__ float sm[];
    float* Upk = sm;                          // 9600 floats
    float* Wpk = sm + 9600;                   // 9600 (FUSED only)
    float* poolf = sm + (FUSED ? 19200 : 9600);
    int tid = threadIdx.x, wid = tid>>5, lane = tid&31;
    u64* h2 = (u64*)poolf + (size_t)wid*(FUSED ? S*128 : S*64);
    u64* x2 = h2 + S*64;                      // FUSED only

    for (int idx = tid; idx < 9600; idx += WARPS*32){
        int g = idx/384, rem = idx - g*384;
        int ro = rem >> 7, rem2 = rem & 127;
        int li = rem2 >> 2, e = rem2 & 3;
        int k = 2*g + (e>>1), ch = li + 32*(e&1);
        float uv = 0.f;
        if (ch < 50) uv = Ug[k*G3 + ro*50 + ch];
        Upk[idx] = uv;
        if (FUSED){
            float wv = 0.f;
            if (ch < 50) wv = Wg[k*G3 + ro*50 + ch];
            Wpk[idx] = wv;
        }
    }

    const bool v2 = lane < 18;
    const int c1 = lane, c2 = lane + 32;
    const int c2v = v2 ? c2 : c1;
    const float* bi = bvec;
    const float* br = bvec + G3;
    u64 bz, brr, bhx, bhr;
    if (FUSED){
        bz  = pack2(bi[c1]+br[c1],       bi[c2v]+br[c2v]);
        brr = pack2(bi[50+c1]+br[50+c1], bi[50+c2v]+br[50+c2v]);
        bhx = pack2(bi[100+c1],          bi[100+c2v]);
        bhr = pack2(br[100+c1],          br[100+c2v]);
    } else {
        bz  = pack2(br[c1],     br[c2v]);
        brr = pack2(br[50+c1],  br[50+c2v]);
        bhx = 0ull;
        bhr = pack2(br[100+c1], br[100+c2v]);
    }
    __syncthreads();   // weights visible to all warps

    for (int grp = blockIdx.x*WARPS + wid; grp < nGroups; grp += gridDim.x*WARPS){
        int q0 = grp*S;
        int b0 = q0 & 63, rr = q0 >> 6;

        u64 hcur[S];
        #pragma unroll
        for (int s=0;s<S;s++){
            hcur[s] = 0ull;
            h2[s*64 + c1] = 0ull;
            h2[s*64 + c2] = 0ull;
        }
        __syncwarp();

        // one-step-ahead prefetch
        float xn1[S], xn2[S];               // FUSED
        u64 gz[S], gr[S], gh[S];            // PRE
        {
            int t_in = rr;
            if (FUSED){
                #pragma unroll
                for (int s=0;s<S;s++){
                    const float* s0 = xin + ((size_t)t_in*64 + b0+s)*HID;
                    xn1[s] = s0[c1]; xn2[s] = s0[c2v];
                }
            } else {
                #pragma unroll
                for (int s=0;s<S;s++){
                    const float* s0 = xin + ((size_t)t_in*64 + b0+s)*XGS;
                    gz[s] = pack2(s0[c1],     s0[c2v]);
                    gr[s] = pack2(s0[50+c1],  s0[50+c2v]);
                    gh[s] = pack2(s0[100+c1], s0[100+c2v]);
                }
            }
        }

        for (int st=0; st<dn; st++){
            u64 az[S], ar[S], ahx[S], ahr[S];
            if (FUSED){
                #pragma unroll
                for (int s=0;s<S;s++){
                    x2[s*64 + c1] = dup2(xn1[s]);
                    x2[s*64 + c2] = dup2(xn2[s]);   // k>=50 slots never read
                    az[s]=bz; ar[s]=brr; ahx[s]=bhx; ahr[s]=bhr;
                }
                __syncwarp();
            } else {
                #pragma unroll
                for (int s=0;s<S;s++){
                    az[s]=bz;  add2(az[s], gz[s]);
                    ar[s]=brr; add2(ar[s], gr[s]);
                    ahx[s]=gh[s];
                    ahr[s]=bhr;
                }
            }
            if (st+1 < dn){
                int t_in = (st+1)*rate + rr;
                if (FUSED){
                    #pragma unroll
                    for (int s=0;s<S;s++){
                        const float* s0 = xin + ((size_t)t_in*64 + b0+s)*HID;
                        xn1[s] = s0[c1]; xn2[s] = s0[c2v];
                    }
                } else {
                    #pragma unroll
                    for (int s=0;s<S;s++){
                        const float* s0 = xin + ((size_t)t_in*64 + b0+s)*XGS;
                        gz[s] = pack2(s0[c1],     s0[c2v]);
                        gr[s] = pack2(s0[50+c1],  s0[50+c2v]);
                        gh[s] = pack2(s0[100+c1], s0[100+c2v]);
                    }
                }
            }
            if (FUSED){
                #pragma unroll 5
                for (int g=0; g<25; g++){
                    const float* wb = Wpk + g*384 + lane*4;
                    ulonglong2 wz = *(const ulonglong2*)(wb);
                    ulonglong2 wr = *(const ulonglong2*)(wb + 128);
                    ulonglong2 wh = *(const ulonglong2*)(wb + 256);
                    #pragma unroll
                    for (int s=0;s<S;s++){
                        ulonglong2 xx = *(const ulonglong2*)(x2 + s*64 + 2*g);
                        fma2(az[s],  xx.x, wz.x); fma2(az[s],  xx.y, wz.y);
                        fma2(ar[s],  xx.x, wr.x); fma2(ar[s],  xx.y, wr.y);
                        fma2(ahx[s], xx.x, wh.x); fma2(ahx[s], xx.y, wh.y);
                    }
                }
            }
            #pragma unroll 5
            for (int g=0; g<25; g++){
                const float* ub = Upk + g*384 + lane*4;
                ulonglong2 uz = *(const ulonglong2*)(ub);
                ulonglong2 ur = *(const ulonglong2*)(ub + 128);
                ulonglong2 uh = *(const ulonglong2*)(ub + 256);
                #pragma unroll
                for (int s=0;s<S;s++){
                    ulonglong2 hh = *(const ulonglong2*)(h2 + s*64 + 2*g);
                    fma2(az[s],  hh.x, uz.x); fma2(az[s],  hh.y, uz.y);
                    fma2(ar[s],  hh.x, ur.x); fma2(ar[s],  hh.y, ur.y);
                    fma2(ahr[s], hh.x, uh.x); fma2(ahr[s], hh.y, uh.y);
                }
            }
            __syncwarp();
            int t_out = rr*dn + st;
            #pragma unroll
            for (int s=0;s<S;s++){
                float* op = out + ((size_t)t_out*64 + b0+s)*HID;
                float2 zz = unp2(az[s]); float z1 = sigt(zz.x), z2 = sigt(zz.y);
                float2 rv = unp2(ar[s]); float r1 = sigt(rv.x), r2 = sigt(rv.y);
                u64 tt = ahx[s]; fma2(tt, pack2(r1,r2), ahr[s]);
                float2 th = unp2(tt);
                float hh1 = tanhf_fast(th.x), hh2 = tanhf_fast(th.y);
                float2 ho = unp2(hcur[s]);
                float hn1 = hh1 + z1*(ho.x - hh1);
                float hn2 = hh2 + z2*(ho.y - hh2);
                hcur[s] = pack2(hn1, hn2);
                h2[s*64 + c1] = dup2(hn1);
                op[c1] = hn1;
                if (v2){
                    h2[s*64 + c2] = dup2(hn2);
                    op[c2] = hn2;
                }
            }
            __syncwarp();
        }
    }
}

// ---------------------------------------------------------------------------
// head: split-K dense2. grid (25, 4); partial[ks][m][n] written un-biased.
// ---------------------------------------------------------------------------
__global__ void __launch_bounds__(256,2)
dense2_kernel(const float* __restrict__ Xf, const float* __restrict__ W2,
              float* __restrict__ h1p)
{
    __shared__ float As[64][52];
    __shared__ float Bs[50][64];
    int tid = threadIdx.x;
    int n0 = blockIdx.x*64;
    int k0 = blockIdx.y*400;
    int tm = tid/16, tn = tid%16;
    float acc[4][4] = {};
    for (int c=0; c<8; c++){
        const float* src = Xf + (size_t)(2016 + k0/50 + c)*(BATCH*HID);
        for (int p=tid; p<64*50; p+=256){
            int m = p/50, kk = p - m*50;
            As[m][kk] = src[p];
        }
        for (int p=tid; p<50*64; p+=256){
            int kk = p/64, n = p - kk*64;
            Bs[kk][n] = W2[(size_t)(k0 + c*50 + kk)*1600 + n0 + n];
        }
        __syncthreads();
        #pragma unroll 10
        for (int kk=0; kk<50; kk++){
            float a[4], bb[4];
            #pragma unroll
            for (int i=0;i<4;i++) a[i]  = As[tm*4+i][kk];
            #pragma unroll
            for (int j=0;j<4;j++) bb[j] = Bs[kk][tn*4+j];
            #pragma unroll
            for (int i=0;i<4;i++)
                #pragma unroll
                for (int j=0;j<4;j++) acc[i][j] += a[i]*bb[j];
        }
        __syncthreads();
    }
    float* outp = h1p + (size_t)blockIdx.y*BATCH*1600;
    #pragma unroll
    for (int i=0;i<4;i++){
        int m = tm*4+i;
        #pragma unroll
        for (int j=0;j<4;j++){
            int n = n0 + tn*4 + j;
            outp[(size_t)m*1600 + n] = acc[i][j];
        }
    }
}

__global__ void __launch_bounds__(64,1)
cls_softmax_kernel(const float* __restrict__ h1p, const float* __restrict__ b2,
                   const float* __restrict__ Wc, const float* __restrict__ bc,
                   float* __restrict__ out)
{
    __shared__ float hs[1600];
    __shared__ float lg[41];
    __shared__ float red[2];
    int b = blockIdx.x, tid = threadIdx.x;
    for (int i=tid; i<1600; i+=64){
        float v = h1p[(size_t)b*1600 + i]
                + h1p[(size_t)BATCH*1600   + (size_t)b*1600 + i]
                + h1p[(size_t)2*BATCH*1600 + (size_t)b*1600 + i]
                + h1p[(size_t)3*BATCH*1600 + (size_t)b*1600 + i]
                + b2[i];
        hs[i] = fmaxf(v, 0.0f);
    }
    __syncthreads();
    if (tid < 41){
        float a0=0.f, a1=0.f, a2=0.f, a3=0.f;
        for (int i=0; i<1600; i+=4){
            a0 += hs[i+0]*Wc[(size_t)(i+0)*41 + tid];
            a1 += hs[i+1]*Wc[(size_t)(i+1)*41 + tid];
            a2 += hs[i+2]*Wc[(size_t)(i+2)*41 + tid];
            a3 += hs[i+3]*Wc[(size_t)(i+3)*41 + tid];
        }
        lg[tid] = (a0+a1) + (a2+a3) + bc[tid];
    }
    __syncthreads();
    if (tid == 0){
        float mx = lg[0];
        for (int o=1;o<41;o++) mx = fmaxf(mx, lg[o]);
        float sum = 0.f;
        for (int o=0;o<41;o++) sum += expf(lg[o]-mx);
        red[0]=mx; red[1]=sum;
    }
    __syncthreads();
    if (tid < 41) out[(size_t)b*41 + tid] = expf(lg[tid]-red[0]) / red[1];
}

// ---------------------------------------------------------------------------
static const int SM_GEMM = (8448 + 5120 + 9728)*4;            // 93184
static const int SM_PRE  = 9600*4 + 4*(2*64)*8;               // 42496 (S=2,W=4)
static const int SM_MID  = 19200*4 + 4*(8*128)*8;             // 109568 (S=8,W=4)

extern "C" void kernel_launch(void* const* d_in, const int* in_sizes, int n_in,
                              void* d_out, int out_size)
{
    const float* x   = (const float*)d_in[0];
    const float* W0  = (const float*)d_in[1];
    const float* U0  = (const float*)d_in[2];
    const float* b0v = (const float*)d_in[3];
    const float* Ws  = (const float*)d_in[4];   // [5][50][150]
    const float* Us  = (const float*)d_in[5];
    const float* bs  = (const float*)d_in[6];   // [5][2][150]
    const float* W2  = (const float*)d_in[7];
    const float* b2  = (const float*)d_in[8];
    const float* Wc  = (const float*)d_in[9];
    const float* bc  = (const float*)d_in[10];
    float* out = (float*)d_out;

    float *buf0, *buf1, *xg, *h1p;
    cudaGetSymbolAddress((void**)&buf0, g_buf0);
    cudaGetSymbolAddress((void**)&buf1, g_buf1);
    cudaGetSymbolAddress((void**)&xg,   g_xg);
    cudaGetSymbolAddress((void**)&h1p,  g_h1);

    cudaFuncSetAttribute(xg_gemm_kernel,
                         cudaFuncAttributeMaxDynamicSharedMemorySize, SM_GEMM);
    cudaFuncSetAttribute(scan_pre_kernel<2,4>,
                         cudaFuncAttributeMaxDynamicSharedMemorySize, SM_PRE);
    cudaFuncSetAttribute(scan_kernel<8,4,true>,
                         cudaFuncAttributeMaxDynamicSharedMemorySize, SM_MID);

    // layer 0: input GEMM (K=128) + recurrent-only scan (champion: S=2, 256)
    xg_gemm_kernel<<<2048, 256, SM_GEMM>>>(x, W0, b0v, xg);
    scan_pre_kernel<2,4><<<256, 128, SM_PRE>>>(xg, U0, b0v, buf0, 32, 64, 1024);

    // layer 1 (rate 64): 512 groups, grid 148 W4 (best measured balance)
    scan_kernel<8,4,true><<<148, 128, SM_MID>>>(
        buf0, Ws + 0*(size_t)HID*G3, Us + 0*(size_t)HID*G3,
        bs + 0*(size_t)2*G3, buf1, 64, 32, 512);

    // layers 2-5: persistent, grid 296 (2 CTAs/SM), warps loop over groups
    const int rates4[4] = {128,256,512,1024};
    float* bufs[2] = {buf1, buf0};   // layer2 in=buf1, out=buf0, alternating
    for (int i=0; i<4; i++){
        int rate = rates4[i], dn = TLEN/rate;
        int nGroups = (rate*BATCH)/8;
        scan_kernel<8,4,true><<<296, 128, SM_MID>>>(
            bufs[i&1], Ws + (size_t)(i+1)*HID*G3, Us + (size_t)(i+1)*HID*G3,
            bs + (size_t)(i+1)*2*G3, bufs[(i+1)&1], rate, dn, nGroups);
    }
    // layer5 (i=3) writes bufs[0] = buf1

    dense2_kernel<<<dim3(25,4), 256>>>(buf1, W2, h1p);
    cls_softmax_kernel<<<64, 64>>>(h1p, b2, Wc, bc, out);
}

// round 17
// speedup vs baseline: 1.5597x; 1.5597x over previous
#include <cuda_runtime.h>
#include <math.h>

#define TLEN 2048
#define BATCH 64
#define HID 50
#define G3 150
#define XGS 152
#define DIN0 128

typedef unsigned long long u64;

// scratch (device globals: allocation-free rule)
__device__ float g_buf0[TLEN*BATCH*HID];
__device__ float g_buf1[TLEN*BATCH*HID];
__device__ float g_xg[TLEN*BATCH*XGS];
__device__ float g_h1[4*BATCH*1600];     // 4 split-K partials

__device__ __forceinline__ float sigf(float x){
    return __fdividef(1.0f, 1.0f + __expf(-x));
}
__device__ __forceinline__ float tanhf_fast(float x){
    float e = __expf(2.0f*x);              // inf-safe
    return 1.0f - __fdividef(2.0f, e + 1.0f);
}
__device__ __forceinline__ void fma2(u64& d, u64 a, u64 b){
    asm("fma.rn.f32x2 %0, %1, %2, %0;" : "+l"(d) : "l"(a), "l"(b));
}
__device__ __forceinline__ void add2(u64& d, u64 a){
    asm("add.rn.f32x2 %0, %0, %1;" : "+l"(d) : "l"(a));
}
__device__ __forceinline__ u64 dup2(float x){
    u64 r; asm("mov.b64 %0, {%1, %1};" : "=l"(r) : "f"(x)); return r;
}
__device__ __forceinline__ u64 pack2(float a, float b){
    u64 r; asm("mov.b64 %0, {%1, %2};" : "=l"(r) : "f"(a), "f"(b)); return r;
}
__device__ __forceinline__ float2 unp2(u64 v){
    float2 r; asm("mov.b64 {%0, %1}, %2;" : "=f"(r.x), "=f"(r.y) : "l"(v)); return r;
}

// ---------------------------------------------------------------------------
// Layer-0 input-gate GEMM (K=128), coalesced stores via smem staging.
// ---------------------------------------------------------------------------
__global__ void __launch_bounds__(256,2)
xg_gemm_kernel(const float* __restrict__ x, const float* __restrict__ W,
               const float* __restrict__ bi, float* __restrict__ xg)
{
    extern __shared__ float sm[];
    float* Xs = sm;                  // 64 x 132
    float* Wk = sm + 8448;           // 32 x 160
    float* Ys = sm + 8448 + 5120;    // 64 x 152
    int t = blockIdx.x;
    int tid = threadIdx.x;
    int tm = tid >> 3;
    int tn = tid & 7;

    for (int p = tid; p < 64*DIN0; p += 256){
        int b = p >> 7, d = p & 127;
        Xs[b*132 + d] = x[(size_t)b*TLEN*DIN0 + (size_t)t*DIN0 + d];
    }
    u64 acc[2][10];
    #pragma unroll
    for (int i=0;i<2;i++)
        #pragma unroll
        for (int j=0;j<10;j++) acc[i][j]=0ull;

    for (int kc = 0; kc < DIN0; kc += 32){
        __syncthreads();
        for (int p = tid; p < 32*160; p += 256){
            int r = p/160, c = p - r*160;
            Wk[p] = (c < G3) ? W[(size_t)(kc+r)*G3 + c] : 0.f;
        }
        __syncthreads();
        #pragma unroll 4
        for (int kk = 0; kk < 32; kk++){
            u64 a0 = dup2(Xs[(2*tm)  *132 + kc+kk]);
            u64 a1 = dup2(Xs[(2*tm+1)*132 + kc+kk]);
            const ulonglong2* bp = (const ulonglong2*)(Wk + kk*160 + tn*20);
            #pragma unroll
            for (int q=0;q<5;q++){
                ulonglong2 w = bp[q];
                fma2(acc[0][2*q],   a0, w.x);
                fma2(acc[0][2*q+1], a0, w.y);
                fma2(acc[1][2*q],   a1, w.x);
                fma2(acc[1][2*q+1], a1, w.y);
            }
        }
    }
    __syncthreads();
    #pragma unroll
    for (int i=0;i<2;i++){
        int row = 2*tm+i;
        #pragma unroll
        for (int q=0;q<10;q++){
            float2 v = unp2(acc[i][q]);
            int c0 = tn*20 + 2*q;
            if (c0 < 152)
                Ys[row*152 + c0]   = (c0   < G3) ? v.x + bi[c0]   : 0.f;
            if (c0+1 < 152)
                Ys[row*152 + c0+1] = (c0+1 < G3) ? v.y + bi[c0+1] : 0.f;
        }
    }
    __syncthreads();
    float4* dst = (float4*)(xg + (size_t)t*64*XGS);
    const float4* srcy = (const float4*)Ys;
    for (int p = tid; p < (64*152)/4; p += 256) dst[p] = srcy[p];
}

// ---------------------------------------------------------------------------
// PRE scan (recurrent-only, gates precomputed). Champion config: S=2, W=4.
// ---------------------------------------------------------------------------
template<int S, int WARPS>
__global__ void __launch_bounds__(WARPS*32, 2)
scan_pre_kernel(const float* __restrict__ xg, const float* __restrict__ Ug,
                const float* __restrict__ bvec, float* __restrict__ out,
                int rate, int dn, int nGroups)
{
    extern __shared__ float sm[];
    float* Upk = sm;                          // 9600 floats
    float* poolf = sm + 9600;
    int tid = threadIdx.x, wid = tid>>5, lane = tid&31;
    u64* h2 = (u64*)poolf + (size_t)wid*(S*64);

    for (int idx = tid; idx < 9600; idx += WARPS*32){
        int g = idx/384, rem = idx - g*384;
        int ro = rem >> 7, rem2 = rem & 127;
        int li = rem2 >> 2, e = rem2 & 3;
        int k = 2*g + (e>>1), ch = li + 32*(e&1);
        Upk[idx] = (ch < 50) ? Ug[k*G3 + ro*50 + ch] : 0.f;
    }
    const bool v2 = lane < 18;
    const int c1 = lane, c2 = lane + 32;
    const int c2v = v2 ? c2 : c1;
    const float* br = bvec + G3;
    u64 bz  = pack2(br[c1],     br[c2v]);
    u64 brr = pack2(br[50+c1],  br[50+c2v]);
    u64 bhr = pack2(br[100+c1], br[100+c2v]);
    __syncthreads();

    for (int grp = blockIdx.x*WARPS + wid; grp < nGroups; grp += gridDim.x*WARPS){
        int q0 = grp*S;
        int b0 = q0 & 63, rr = q0 >> 6;
        u64 hcur[S];
        #pragma unroll
        for (int s=0;s<S;s++){
            hcur[s] = 0ull;
            h2[s*64 + c1] = 0ull;
            h2[s*64 + c2] = 0ull;
        }
        __syncwarp();
        u64 gz[S], gr[S], gh[S];
        #pragma unroll
        for (int s=0;s<S;s++){
            const float* s0 = xg + ((size_t)rr*64 + b0+s)*XGS;
            gz[s] = pack2(s0[c1],     s0[c2v]);
            gr[s] = pack2(s0[50+c1],  s0[50+c2v]);
            gh[s] = pack2(s0[100+c1], s0[100+c2v]);
        }
        for (int st=0; st<dn; st++){
            u64 az[S], ar[S], ahx[S], ahr[S];
            #pragma unroll
            for (int s=0;s<S;s++){
                az[s]=bz;  add2(az[s], gz[s]);
                ar[s]=brr; add2(ar[s], gr[s]);
                ahx[s]=gh[s];
                ahr[s]=bhr;
            }
            if (st+1 < dn){
                int t_in = (st+1)*rate + rr;
                #pragma unroll
                for (int s=0;s<S;s++){
                    const float* s0 = xg + ((size_t)t_in*64 + b0+s)*XGS;
                    gz[s] = pack2(s0[c1],     s0[c2v]);
                    gr[s] = pack2(s0[50+c1],  s0[50+c2v]);
                    gh[s] = pack2(s0[100+c1], s0[100+c2v]);
                }
            }
            #pragma unroll 5
            for (int g=0; g<25; g++){
                const float* ub = Upk + g*384 + lane*4;
                ulonglong2 uz = *(const ulonglong2*)(ub);
                ulonglong2 ur = *(const ulonglong2*)(ub + 128);
                ulonglong2 uh = *(const ulonglong2*)(ub + 256);
                #pragma unroll
                for (int s=0;s<S;s++){
                    ulonglong2 hh = *(const ulonglong2*)(h2 + s*64 + 2*g);
                    fma2(az[s],  hh.x, uz.x); fma2(az[s],  hh.y, uz.y);
                    fma2(ar[s],  hh.x, ur.x); fma2(ar[s],  hh.y, ur.y);
                    fma2(ahr[s], hh.x, uh.x); fma2(ahr[s], hh.y, uh.y);
                }
            }
            __syncwarp();
            int t_out = rr*dn + st;
            #pragma unroll
            for (int s=0;s<S;s++){
                float* op = out + ((size_t)t_out*64 + b0+s)*HID;
                float2 zz = unp2(az[s]); float z1 = sigf(zz.x), z2 = sigf(zz.y);
                float2 rv = unp2(ar[s]); float r1 = sigf(rv.x), r2 = sigf(rv.y);
                u64 tt = ahx[s]; fma2(tt, pack2(r1,r2), ahr[s]);
                float2 th = unp2(tt);
                float hh1 = tanhf_fast(th.x), hh2 = tanhf_fast(th.y);
                float2 ho = unp2(hcur[s]);
                float hn1 = hh1 + z1*(ho.x - hh1);
                float hn2 = hh2 + z2*(ho.y - hh2);
                hcur[s] = pack2(hn1, hn2);
                h2[s*64 + c1] = dup2(hn1);
                op[c1] = hn1;
                if (v2){
                    h2[s*64 + c2] = dup2(hn2);
                    op[c2] = hn2;
                }
            }
            __syncwarp();
        }
    }
}

// ---------------------------------------------------------------------------
// Persistent fused dilated-GRU scan (champion inner loops, hcur in regs).
// ---------------------------------------------------------------------------
template<int S, int WARPS, bool FUSED>
__global__ void __launch_bounds__(WARPS*32, 2)
scan_kernel(const float* __restrict__ xin, const float* __restrict__ Wg,
            const float* __restrict__ Ug, const float* __restrict__ bvec,
            float* __restrict__ out, int rate, int dn, int nGroups)
{
    extern __shared__ float sm[];
    float* Upk = sm;                          // 9600 floats
    float* Wpk = sm + 9600;                   // 9600 (FUSED only)
    float* poolf = sm + (FUSED ? 19200 : 9600);
    int tid = threadIdx.x, wid = tid>>5, lane = tid&31;
    u64* h2 = (u64*)poolf + (size_t)wid*(FUSED ? S*128 : S*64);
    u64* x2 = h2 + S*64;                      // FUSED only

    for (int idx = tid; idx < 9600; idx += WARPS*32){
        int g = idx/384, rem = idx - g*384;
        int ro = rem >> 7, rem2 = rem & 127;
        int li = rem2 >> 2, e = rem2 & 3;
        int k = 2*g + (e>>1), ch = li + 32*(e&1);
        float uv = 0.f;
        if (ch < 50) uv = Ug[k*G3 + ro*50 + ch];
        Upk[idx] = uv;
        if (FUSED){
            float wv = 0.f;
            if (ch < 50) wv = Wg[k*G3 + ro*50 + ch];
            Wpk[idx] = wv;
        }
    }

    const bool v2 = lane < 18;
    const int c1 = lane, c2 = lane + 32;
    const int c2v = v2 ? c2 : c1;
    const float* bi = bvec;
    const float* br = bvec + G3;
    u64 bz, brr, bhx, bhr;
    if (FUSED){
        bz  = pack2(bi[c1]+br[c1],       bi[c2v]+br[c2v]);
        brr = pack2(bi[50+c1]+br[50+c1], bi[50+c2v]+br[50+c2v]);
        bhx = pack2(bi[100+c1],          bi[100+c2v]);
        bhr = pack2(br[100+c1],          br[100+c2v]);
    } else {
        bz  = pack2(br[c1],     br[c2v]);
        brr = pack2(br[50+c1],  br[50+c2v]);
        bhx = 0ull;
        bhr = pack2(br[100+c1], br[100+c2v]);
    }
    __syncthreads();   // weights visible to all warps

    for (int grp = blockIdx.x*WARPS + wid; grp < nGroups; grp += gridDim.x*WARPS){
        int q0 = grp*S;
        int b0 = q0 & 63, rr = q0 >> 6;

        u64 hcur[S];
        #pragma unroll
        for (int s=0;s<S;s++){
            hcur[s] = 0ull;
            h2[s*64 + c1] = 0ull;
            h2[s*64 + c2] = 0ull;
        }
        __syncwarp();

        // one-step-ahead prefetch
        float xn1[S], xn2[S];               // FUSED
        u64 gz[S], gr[S], gh[S];            // PRE
        {
            int t_in = rr;
            if (FUSED){
                #pragma unroll
                for (int s=0;s<S;s++){
                    const float* s0 = xin + ((size_t)t_in*64 + b0+s)*HID;
                    xn1[s] = s0[c1]; xn2[s] = s0[c2v];
                }
            } else {
                #pragma unroll
                for (int s=0;s<S;s++){
                    const float* s0 = xin + ((size_t)t_in*64 + b0+s)*XGS;
                    gz[s] = pack2(s0[c1],     s0[c2v]);
                    gr[s] = pack2(s0[50+c1],  s0[50+c2v]);
                    gh[s] = pack2(s0[100+c1], s0[100+c2v]);
                }
            }
        }

        for (int st=0; st<dn; st++){
            u64 az[S], ar[S], ahx[S], ahr[S];
            if (FUSED){
                #pragma unroll
                for (int s=0;s<S;s++){
                    x2[s*64 + c1] = dup2(xn1[s]);
                    x2[s*64 + c2] = dup2(xn2[s]);   // k>=50 slots never read
                    az[s]=bz; ar[s]=brr; ahx[s]=bhx; ahr[s]=bhr;
                }
                __syncwarp();
            } else {
                #pragma unroll
                for (int s=0;s<S;s++){
                    az[s]=bz;  add2(az[s], gz[s]);
                    ar[s]=brr; add2(ar[s], gr[s]);
                    ahx[s]=gh[s];
                    ahr[s]=bhr;
                }
            }
            if (st+1 < dn){
                int t_in = (st+1)*rate + rr;
                if (FUSED){
                    #pragma unroll
                    for (int s=0;s<S;s++){
                        const float* s0 = xin + ((size_t)t_in*64 + b0+s)*HID;
                        xn1[s] = s0[c1]; xn2[s] = s0[c2v];
                    }
                } else {
                    #pragma unroll
                    for (int s=0;s<S;s++){
                        const float* s0 = xin + ((size_t)t_in*64 + b0+s)*XGS;
                        gz[s] = pack2(s0[c1],     s0[c2v]);
                        gr[s] = pack2(s0[50+c1],  s0[50+c2v]);
                        gh[s] = pack2(s0[100+c1], s0[100+c2v]);
                    }
                }
            }
            if (FUSED){
                #pragma unroll 5
                for (int g=0; g<25; g++){
                    const float* wb = Wpk + g*384 + lane*4;
                    ulonglong2 wz = *(const ulonglong2*)(wb);
                    ulonglong2 wr = *(const ulonglong2*)(wb + 128);
                    ulonglong2 wh = *(const ulonglong2*)(wb + 256);
                    #pragma unroll
                    for (int s=0;s<S;s++){
                        ulonglong2 xx = *(const ulonglong2*)(x2 + s*64 + 2*g);
                        fma2(az[s],  xx.x, wz.x); fma2(az[s],  xx.y, wz.y);
                        fma2(ar[s],  xx.x, wr.x); fma2(ar[s],  xx.y, wr.y);
                        fma2(ahx[s], xx.x, wh.x); fma2(ahx[s], xx.y, wh.y);
                    }
                }
            }
            #pragma unroll 5
            for (int g=0; g<25; g++){
                const float* ub = Upk + g*384 + lane*4;
                ulonglong2 uz = *(const ulonglong2*)(ub);
                ulonglong2 ur = *(const ulonglong2*)(ub + 128);
                ulonglong2 uh = *(const ulonglong2*)(ub + 256);
                #pragma unroll
                for (int s=0;s<S;s++){
                    ulonglong2 hh = *(const ulonglong2*)(h2 + s*64 + 2*g);
                    fma2(az[s],  hh.x, uz.x); fma2(az[s],  hh.y, uz.y);
                    fma2(ar[s],  hh.x, ur.x); fma2(ar[s],  hh.y, ur.y);
                    fma2(ahr[s], hh.x, uh.x); fma2(ahr[s], hh.y, uh.y);
                }
            }
            __syncwarp();
            int t_out = rr*dn + st;
            #pragma unroll
            for (int s=0;s<S;s++){
                float* op = out + ((size_t)t_out*64 + b0+s)*HID;
                float2 zz = unp2(az[s]); float z1 = sigf(zz.x), z2 = sigf(zz.y);
                float2 rv = unp2(ar[s]); float r1 = sigf(rv.x), r2 = sigf(rv.y);
                u64 tt = ahx[s]; fma2(tt, pack2(r1,r2), ahr[s]);
                float2 th = unp2(tt);
                float hh1 = tanhf_fast(th.x), hh2 = tanhf_fast(th.y);
                float2 ho = unp2(hcur[s]);
                float hn1 = hh1 + z1*(ho.x - hh1);
                float hn2 = hh2 + z2*(ho.y - hh2);
                hcur[s] = pack2(hn1, hn2);
                h2[s*64 + c1] = dup2(hn1);
                op[c1] = hn1;
                if (v2){
                    h2[s*64 + c2] = dup2(hn2);
                    op[c2] = hn2;
                }
            }
            __syncwarp();
        }
    }
}

// ---------------------------------------------------------------------------
// head: split-K dense2. grid (25, 4); partial[ks][m][n] written un-biased.
// ---------------------------------------------------------------------------
__global__ void __launch_bounds__(256,2)
dense2_kernel(const float* __restrict__ Xf, const float* __restrict__ W2,
              float* __restrict__ h1p)
{
    __shared__ float As[64][52];
    __shared__ float Bs[50][64];
    int tid = threadIdx.x;
    int n0 = blockIdx.x*64;
    int k0 = blockIdx.y*400;
    int tm = tid/16, tn = tid%16;
    float acc[4][4] = {};
    for (int c=0; c<8; c++){
        const float* src = Xf + (size_t)(2016 + k0/50 + c)*(BATCH*HID);
        for (int p=tid; p<64*50; p+=256){
            int m = p/50, kk = p - m*50;
            As[m][kk] = src[p];
        }
        for (int p=tid; p<50*64; p+=256){
            int kk = p/64, n = p - kk*64;
            Bs[kk][n] = W2[(size_t)(k0 + c*50 + kk)*1600 + n0 + n];
        }
        __syncthreads();
        #pragma unroll 10
        for (int kk=0; kk<50; kk++){
            float a[4], bb[4];
            #pragma unroll
            for (int i=0;i<4;i++) a[i]  = As[tm*4+i][kk];
            #pragma unroll
            for (int j=0;j<4;j++) bb[j] = Bs[kk][tn*4+j];
            #pragma unroll
            for (int i=0;i<4;i++)
                #pragma unroll
                for (int j=0;j<4;j++) acc[i][j] += a[i]*bb[j];
        }
        __syncthreads();
    }
    float* outp = h1p + (size_t)blockIdx.y*BATCH*1600;
    #pragma unroll
    for (int i=0;i<4;i++){
        int m = tm*4+i;
        #pragma unroll
        for (int j=0;j<4;j++){
            int n = n0 + tn*4 + j;
            outp[(size_t)m*1600 + n] = acc[i][j];
        }
    }
}

__global__ void __launch_bounds__(64,1)
cls_softmax_kernel(const float* __restrict__ h1p, const float* __restrict__ b2,
                   const float* __restrict__ Wc, const float* __restrict__ bc,
                   float* __restrict__ out)
{
    __shared__ float hs[1600];
    __shared__ float lg[41];
    __shared__ float red[2];
    int b = blockIdx.x, tid = threadIdx.x;
    for (int i=tid; i<1600; i+=64){
        float v = h1p[(size_t)b*1600 + i]
                + h1p[(size_t)BATCH*1600   + (size_t)b*1600 + i]
                + h1p[(size_t)2*BATCH*1600 + (size_t)b*1600 + i]
                + h1p[(size_t)3*BATCH*1600 + (size_t)b*1600 + i]
                + b2[i];
        hs[i] = fmaxf(v, 0.0f);
    }
    __syncthreads();
    if (tid < 41){
        float a0=0.f, a1=0.f, a2=0.f, a3=0.f;
        for (int i=0; i<1600; i+=4){
            a0 += hs[i+0]*Wc[(size_t)(i+0)*41 + tid];
            a1 += hs[i+1]*Wc[(size_t)(i+1)*41 + tid];
            a2 += hs[i+2]*Wc[(size_t)(i+2)*41 + tid];
            a3 += hs[i+3]*Wc[(size_t)(i+3)*41 + tid];
        }
        lg[tid] = (a0+a1) + (a2+a3) + bc[tid];
    }
    __syncthreads();
    if (tid == 0){
        float mx = lg[0];
        for (int o=1;o<41;o++) mx = fmaxf(mx, lg[o]);
        float sum = 0.f;
        for (int o=0;o<41;o++) sum += expf(lg[o]-mx);
        red[0]=mx; red[1]=sum;
    }
    __syncthreads();
    if (tid < 41) out[(size_t)b*41 + tid] = expf(lg[tid]-red[0]) / red[1];
}

// ---------------------------------------------------------------------------
static const int SM_GEMM = (8448 + 5120 + 9728)*4;            // 93184
static const int SM_PRE  = 9600*4 + 4*(2*64)*8;               // 42496 (S=2,W=4)
static const int SM_MID  = 19200*4 + 4*(8*128)*8;             // 109568 (S=8,W=4)

extern "C" void kernel_launch(void* const* d_in, const int* in_sizes, int n_in,
                              void* d_out, int out_size)
{
    const float* x   = (const float*)d_in[0];
    const float* W0  = (const float*)d_in[1];
    const float* U0  = (const float*)d_in[2];
    const float* b0v = (const float*)d_in[3];
    const float* Ws  = (const float*)d_in[4];   // [5][50][150]
    const float* Us  = (const float*)d_in[5];
    const float* bs  = (const float*)d_in[6];   // [5][2][150]
    const float* W2  = (const float*)d_in[7];
    const float* b2  = (const float*)d_in[8];
    const float* Wc  = (const float*)d_in[9];
    const float* bc  = (const float*)d_in[10];
    float* out = (float*)d_out;

    float *buf0, *buf1, *xg, *h1p;
    cudaGetSymbolAddress((void**)&buf0, g_buf0);
    cudaGetSymbolAddress((void**)&buf1, g_buf1);
    cudaGetSymbolAddress((void**)&xg,   g_xg);
    cudaGetSymbolAddress((void**)&h1p,  g_h1);

    cudaFuncSetAttribute(xg_gemm_kernel,
                         cudaFuncAttributeMaxDynamicSharedMemorySize, SM_GEMM);
    cudaFuncSetAttribute(scan_pre_kernel<2,4>,
                         cudaFuncAttributeMaxDynamicSharedMemorySize, SM_PRE);
    cudaFuncSetAttribute(scan_kernel<8,4,true>,
                         cudaFuncAttributeMaxDynamicSharedMemorySize, SM_MID);

    // layer 0: input GEMM (K=128) + recurrent-only scan (champion: S=2, 256)
    xg_gemm_kernel<<<2048, 256, SM_GEMM>>>(x, W0, b0v, xg);
    scan_pre_kernel<2,4><<<256, 128, SM_PRE>>>(xg, U0, b0v, buf0, 32, 64, 1024);

    // layer 1 (rate 64): 512 groups, grid 148 W4 (best measured balance)
    scan_kernel<8,4,true><<<148, 128, SM_MID>>>(
        buf0, Ws + 0*(size_t)HID*G3, Us + 0*(size_t)HID*G3,
        bs + 0*(size_t)2*G3, buf1, 64, 32, 512);

    // layers 2-5: persistent, grid 296 (2 CTAs/SM), warps loop over groups
    const int rates4[4] = {128,256,512,1024};
    float* bufs[2] = {buf1, buf0};   // layer2 in=buf1, out=buf0, alternating
    for (int i=0; i<4; i++){
        int rate = rates4[i], dn = TLEN/rate;
        int nGroups = (rate*BATCH)/8;
        scan_kernel<8,4,true><<<296, 128, SM_MID>>>(
            bufs[i&1], Ws + (size_t)(i+1)*HID*G3, Us + (size_t)(i+1)*HID*G3,
            bs + (size_t)(i+1)*2*G3, bufs[(i+1)&1], rate, dn, nGroups);
    }
    // layer5 (i=3) writes bufs[0] = buf1

    dense2_kernel<<<dim3(25,4), 256>>>(buf1, W2, h1p);
    cls_softmax_kernel<<<64, 64>>>(h1p, b2, Wc, bc, out);
}